// round 1
// baseline (speedup 1.0000x reference)
#include <cuda_runtime.h>
#include <cstdint>

#define NN 65536

// ---------------- scratch (device globals; no allocation allowed) ----------------
__device__ float g_U[128 * 384];              // folded s-path weights  [k][384]
__device__ float g_V[128 * 512];              // folded v-path weights  [k][512]
__device__ float g_Y[(size_t)NN * 384];       // Y = s @ U              [n][384]
__device__ float g_Z[(size_t)NN * 1536];      // Z[a] = v_a @ V         [n][a][512]

// ---------------- prep: fold W_up, tp_w, CG norms, W_l into U/V ----------------
__global__ void prep_kernel(const float* __restrict__ Wup0, const float* __restrict__ Wup1,
                            const float* __restrict__ tpw,  const float* __restrict__ Wl0,
                            const float* __restrict__ Wl1,  const float* __restrict__ Wl2) {
    const float INV_UP = 0.0883883476483184f;   // 1/sqrt(128)
    const float A2 = 0.7071067811865476f;       // 1/sqrt(2)
    const float A3 = 0.5773502691896258f;       // 1/sqrt(3)
    const float N0 = 0.0625f;                   // 1/sqrt(256)
    const float N1 = 0.0510310363079829f;       // 1/sqrt(384)
    const float R3 = 0.5773502691896258f;       // CG 1/sqrt(3)
    const float R5 = 0.4472135954999579f;       // CG 1/sqrt(5)

    int col = blockIdx.x;      // 0..895 : 0..383 -> U, 384..895 -> V
    int u = threadIdx.x;       // 0..127 (doubles as k in the reduction)
    __shared__ float sw[128];

    float coef, wlv;
    if (col < 384) {
        int j = col >> 7; int v = col & 127;
        if (j == 0)      { coef = A2 * N0 * tpw[0 * 128 + u];      wlv = Wl0[u * 128 + v]; }
        else if (j == 1) { coef = A3 * N1 * R3 * tpw[1 * 128 + u]; wlv = Wl1[u * 128 + v]; }
        else             { coef = A2 * N0 * R5 * tpw[2 * 128 + u]; wlv = Wl2[u * 128 + v]; }
    } else {
        int cc = col - 384; int j = cc >> 7; int v = cc & 127;
        if (j == 0)      { coef = A2 * N0 * R3 * tpw[4 * 128 + u]; wlv = Wl0[(128 + u) * 128 + v]; }
        else if (j == 1) { coef = A3 * N1 * R3 * tpw[3 * 128 + u]; wlv = Wl1[(128 + u) * 128 + v]; }
        else if (j == 2) { coef = A3 * N1 * tpw[6 * 128 + u];      wlv = Wl1[(256 + u) * 128 + v]; }
        else             { coef = A2 * N0 * tpw[5 * 128 + u];      wlv = Wl2[(128 + u) * 128 + v]; }
    }
    sw[u] = coef * wlv;
    __syncthreads();

    const float* Wup = (col < 384) ? Wup0 : Wup1;
    float acc = 0.f;
#pragma unroll 8
    for (int kk = 0; kk < 128; kk++) acc += Wup[u * 128 + kk] * sw[kk];
    acc *= INV_UP;

    if (col < 384) g_U[u * 384 + col] = acc;
    else           g_V[u * 512 + (col - 384)] = acc;
}

// ---------------- main GEMMs: Y = s@U (z=0), Z_a = v_a@V (z=1..3) ----------------
__global__ void __launch_bounds__(256) gemm_kernel(const float* __restrict__ nf) {
    int z = blockIdx.z;                       // 0: s-path, 1..3: v component a=z-1
    int Ncols = (z == 0) ? 384 : 512;
    int ct = blockIdx.y;
    if (ct * 64 >= Ncols) return;
    const float* B = (z == 0) ? g_U : g_V;
    int nodeBase = blockIdx.x * 64;
    int tid = threadIdx.x;

    __shared__ float As[64][132];             // [node][k], padded
    __shared__ float Bs[128][64];             // [k][col]

    if (z == 0) {
#pragma unroll
        for (int i = 0; i < 8; i++) {
            int idx = i * 256 + tid;
            int node = idx >> 5, k4 = idx & 31;
            float4 val = *reinterpret_cast<const float4*>(nf + (size_t)(nodeBase + node) * 512 + k4 * 4);
            *reinterpret_cast<float4*>(&As[node][k4 * 4]) = val;
        }
    } else {
        int a = z - 1;
#pragma unroll
        for (int i = 0; i < 32; i++) {
            int idx = i * 256 + tid;
            int node = idx >> 7, k = idx & 127;
            As[node][k] = nf[(size_t)(nodeBase + node) * 512 + 128 + 3 * k + a];
        }
    }
#pragma unroll
    for (int i = 0; i < 8; i++) {
        int idx = i * 256 + tid;
        int k = idx >> 4, c4 = idx & 15;
        *reinterpret_cast<float4*>(&Bs[k][c4 * 4]) =
            *reinterpret_cast<const float4*>(B + k * Ncols + ct * 64 + c4 * 4);
    }
    __syncthreads();

    int tx = tid & 15, ty = tid >> 4;
    float acc[4][4];
#pragma unroll
    for (int r = 0; r < 4; r++)
#pragma unroll
        for (int c = 0; c < 4; c++) acc[r][c] = 0.f;

#pragma unroll 4
    for (int k = 0; k < 128; k++) {
        float4 b = *reinterpret_cast<const float4*>(&Bs[k][tx * 4]);
        float a0 = As[ty * 4 + 0][k];
        float a1 = As[ty * 4 + 1][k];
        float a2 = As[ty * 4 + 2][k];
        float a3 = As[ty * 4 + 3][k];
        acc[0][0] += a0 * b.x; acc[0][1] += a0 * b.y; acc[0][2] += a0 * b.z; acc[0][3] += a0 * b.w;
        acc[1][0] += a1 * b.x; acc[1][1] += a1 * b.y; acc[1][2] += a1 * b.z; acc[1][3] += a1 * b.w;
        acc[2][0] += a2 * b.x; acc[2][1] += a2 * b.y; acc[2][2] += a2 * b.z; acc[2][3] += a2 * b.w;
        acc[3][0] += a3 * b.x; acc[3][1] += a3 * b.y; acc[3][2] += a3 * b.z; acc[3][3] += a3 * b.w;
    }

    float* C; size_t ldc;
    if (z == 0) { C = g_Y; ldc = 384; }
    else        { C = g_Z + (size_t)(z - 1) * 512; ldc = 1536; }
    size_t colBase = (size_t)ct * 64 + tx * 4;
#pragma unroll
    for (int r = 0; r < 4; r++) {
        size_t row = nodeBase + ty * 4 + r;
        float4 v4 = make_float4(acc[r][0], acc[r][1], acc[r][2], acc[r][3]);
        *reinterpret_cast<float4*>(C + row * ldc + colBase) = v4;
    }
}

// ---------------- combine: mix GEMM outputs with multipole scalars ----------------
__global__ void combine_kernel(const float* __restrict__ mf, float* __restrict__ out) {
    int n = blockIdx.x;
    int v = threadIdx.x;
    __shared__ __align__(16) float so[1152];

    const float* f = mf + (size_t)n * 9;
    float f0  = f[0];
    float f1a = f[1], f1b = f[2], f1c = f[3];
    float f2a = f[4], f2b = f[5], f2c = f[6], f2d = f[7], f2e = f[8];

    const float* Y = g_Y + (size_t)n * 384 + v;
    float y0 = Y[0], y1 = Y[128], y2 = Y[256];
    const float* Z = g_Z + (size_t)n * 1536 + v;
    // z[a][j] = Z[a*512 + j*128]
    float z00 = Z[0],   z10 = Z[512],  z20 = Z[1024];   // j=0: o0 vector path
    float z01 = Z[128], z11 = Z[640],  z21 = Z[1152];   // j=1: o1 f0 path
    float z02 = Z[256], z12 = Z[768],  z22 = Z[1280];   // j=2: o1 C121 path
    float z03 = Z[384], z13 = Z[896],  z23 = Z[1408];   // j=3: o2 C112 path

    const float r2 = 0.7071067811865476f;   // 1/sqrt(2)
    const float r6 = 0.4082482904638631f;   // 1/sqrt(6)
    const float i5 = 0.4472135954999579f;   // 1/sqrt(5)

    // symmetric matrix reconstructed from f2 (indices 0,1,2 = y,z,x basis)
    float A00 = -f2c * r6 - f2e * r2;
    float A11 = 2.f * f2c * r6;
    float A22 = -f2c * r6 + f2e * r2;
    float A01 = f2b * r2, A02 = f2a * r2, A12 = f2d * r2;

    float o0 = f0 * y0 + f1a * z00 + f1b * z10 + f1c * z20;

    float o1_0 = f1a * y1 + f0 * z01 + i5 * (A00 * z02 + A01 * z12 + A02 * z22);
    float o1_1 = f1b * y1 + f0 * z11 + i5 * (A01 * z02 + A11 * z12 + A12 * z22);
    float o1_2 = f1c * y1 + f0 * z21 + i5 * (A02 * z02 + A12 * z12 + A22 * z22);

    float o2_0 = f2a * y2 + i5 * (f1c * r2 * z03 + f1a * r2 * z23);
    float o2_1 = f2b * y2 + i5 * (f1b * r2 * z03 + f1a * r2 * z13);
    float o2_2 = f2c * y2 + i5 * ((-f1a * z03 + 2.f * f1b * z13 - f1c * z23) * r6);
    float o2_3 = f2d * y2 + i5 * (f1c * r2 * z13 + f1b * r2 * z23);
    float o2_4 = f2e * y2 + i5 * ((-f1a * z03 + f1c * z23) * r2);

    float* s = so + v * 9;
    s[0] = o0;
    s[1] = o1_0; s[2] = o1_1; s[3] = o1_2;
    s[4] = o2_0; s[5] = o2_1; s[6] = o2_2; s[7] = o2_3; s[8] = o2_4;
    __syncthreads();

    float4* o4 = reinterpret_cast<float4*>(out + (size_t)n * 1152);
    const float4* s4 = reinterpret_cast<const float4*>(so);
#pragma unroll
    for (int i = v; i < 288; i += 128) o4[i] = s4[i];
}

// ---------------- launch ----------------
extern "C" void kernel_launch(void* const* d_in, const int* in_sizes, int n_in,
                              void* d_out, int out_size) {
    const float* nf   = (const float*)d_in[0];
    const float* mf   = (const float*)d_in[1];
    const float* Wup0 = (const float*)d_in[2];
    const float* Wup1 = (const float*)d_in[3];
    const float* tpw  = (const float*)d_in[4];
    const float* Wl0  = (const float*)d_in[5];
    const float* Wl1  = (const float*)d_in[6];
    const float* Wl2  = (const float*)d_in[7];
    float* out = (float*)d_out;

    prep_kernel<<<896, 128>>>(Wup0, Wup1, tpw, Wl0, Wl1, Wl2);
    gemm_kernel<<<dim3(NN / 64, 8, 4), 256>>>(nf);
    combine_kernel<<<NN, 128>>>(mf, out);
}

// round 2
// speedup vs baseline: 1.2565x; 1.2565x over previous
#include <cuda_runtime.h>
#include <cstdint>

#define NN 65536

// ---------------- scratch (device globals; no allocation allowed) ----------------
__device__ float g_U[128 * 384];              // folded s-path weights  [k][384]
__device__ float g_V[128 * 512];              // folded v-path weights  [k][512]
__device__ float g_Y[(size_t)NN * 384];       // Y = s @ U              [n][384]
__device__ float g_Z[(size_t)NN * 1536];      // Z[a] = v_a @ V         [n][a][512]

// ---------------- prep: fold W_up, tp_w, CG norms, W_l into U/V ----------------
// grid: 56 blocks = 7 sections x 8 u-tiles of 16; 128 threads (v)
__global__ void prep_kernel(const float* __restrict__ Wup0, const float* __restrict__ Wup1,
                            const float* __restrict__ tpw,  const float* __restrict__ Wl0,
                            const float* __restrict__ Wl1,  const float* __restrict__ Wl2) {
    const float INV_UP = 0.0883883476483184f;   // 1/sqrt(128)
    const float A2 = 0.7071067811865476f;       // 1/sqrt(2)
    const float A3 = 0.5773502691896258f;       // 1/sqrt(3)
    const float N0 = 0.0625f;                   // 1/sqrt(256)
    const float N1 = 0.0510310363079829f;       // 1/sqrt(384)
    const float R3 = 0.5773502691896258f;       // CG 1/sqrt(3)
    const float R5 = 0.4472135954999579f;       // CG 1/sqrt(5)

    int sec = blockIdx.x % 7;
    int ut  = blockIdx.x / 7;      // u-tile: rows ut*16 .. +15
    int v   = threadIdx.x;         // 0..127

    float coefBase; const float* Wl; int rowOff; int tpwIdx;
    switch (sec) {
        case 0: coefBase = A2 * N0;      Wl = Wl0; rowOff = 0;   tpwIdx = 0; break;
        case 1: coefBase = A3 * N1 * R3; Wl = Wl1; rowOff = 0;   tpwIdx = 1; break;
        case 2: coefBase = A2 * N0 * R5; Wl = Wl2; rowOff = 0;   tpwIdx = 2; break;
        case 3: coefBase = A2 * N0 * R3; Wl = Wl0; rowOff = 128; tpwIdx = 4; break;
        case 4: coefBase = A3 * N1 * R3; Wl = Wl1; rowOff = 128; tpwIdx = 3; break;
        case 5: coefBase = A3 * N1;      Wl = Wl1; rowOff = 256; tpwIdx = 6; break;
        default:coefBase = A2 * N0;      Wl = Wl2; rowOff = 128; tpwIdx = 5; break;
    }
    const float* Wup = (sec < 3) ? Wup0 : Wup1;

    __shared__ float Ds[64][128];
    float acc[16];
#pragma unroll
    for (int i = 0; i < 16; i++) acc[i] = 0.f;

    for (int kt = 0; kt < 2; kt++) {
        // stage D[k][v] = coef(k) * Wl[rowOff+k][v] for k in this tile (coalesced over v)
        for (int kk = 0; kk < 64; kk++) {
            int k = kt * 64 + kk;
            Ds[kk][v] = coefBase * tpw[tpwIdx * 128 + k] * Wl[(size_t)(rowOff + k) * 128 + v];
        }
        __syncthreads();
#pragma unroll
        for (int uu = 0; uu < 16; uu++) {
            const float* wrow = Wup + (size_t)(ut * 16 + uu) * 128 + kt * 64;
            float a = acc[uu];
#pragma unroll 8
            for (int kk = 0; kk < 64; kk++) a += wrow[kk] * Ds[kk][v];  // wrow: warp-uniform broadcast
            acc[uu] = a;
        }
        __syncthreads();
    }
#pragma unroll
    for (int uu = 0; uu < 16; uu++) {
        int u = ut * 16 + uu;
        float val = acc[uu] * INV_UP;
        if (sec < 3) g_U[u * 384 + sec * 128 + v] = val;
        else         g_V[u * 512 + (sec - 3) * 128 + v] = val;
    }
}

// ---------------- tf32 tensor-core GEMM ----------------
// Y = s@U (z=0, 384 cols), Z_a = v_a@V (z=1..3, 512 cols)
// block tile: 128 nodes x 64 cols, K=128 fully resident. 8 warps, warp tile 32x32.
#define LDA 132
#define LDB 72

__device__ __forceinline__ uint32_t f2tf32(float f) {
    uint32_t u;
    asm("cvt.rna.tf32.f32 %0, %1;" : "=r"(u) : "f"(f));
    return u;
}

__device__ __forceinline__ void mma_tf32(float* d, const uint32_t* a, const uint32_t* b) {
    asm volatile(
        "mma.sync.aligned.m16n8k8.row.col.f32.tf32.tf32.f32 "
        "{%0,%1,%2,%3}, {%4,%5,%6,%7}, {%8,%9}, {%0,%1,%2,%3};"
        : "+f"(d[0]), "+f"(d[1]), "+f"(d[2]), "+f"(d[3])
        : "r"(a[0]), "r"(a[1]), "r"(a[2]), "r"(a[3]), "r"(b[0]), "r"(b[1]));
}

__global__ void __launch_bounds__(256) gemm_tc(const float* __restrict__ nf) {
    extern __shared__ uint32_t smem[];
    uint32_t* As = smem;                 // [128][LDA]
    uint32_t* Bs = smem + 128 * LDA;     // [128][LDB]

    int z = blockIdx.z;
    int Ncols = (z == 0) ? 384 : 512;
    int ct = blockIdx.y;
    if (ct * 64 >= Ncols) return;
    const float* B = (z == 0) ? g_U : g_V;
    int nodeBase = blockIdx.x * 128;
    int tid = threadIdx.x;

    // ---- stage A (128 nodes x 128 k) as tf32 ----
    if (z == 0) {
#pragma unroll
        for (int i = 0; i < 16; i++) {
            int idx = i * 256 + tid;               // float4 index
            int node = idx >> 5, k4 = idx & 31;
            float4 val = *reinterpret_cast<const float4*>(
                nf + (size_t)(nodeBase + node) * 512 + k4 * 4);
            uint4 o = make_uint4(f2tf32(val.x), f2tf32(val.y), f2tf32(val.z), f2tf32(val.w));
            *reinterpret_cast<uint4*>(&As[node * LDA + k4 * 4]) = o;
        }
    } else {
        int a = z - 1;
#pragma unroll
        for (int i = 0; i < 64; i++) {
            int idx = i * 256 + tid;
            int node = idx >> 7, k = idx & 127;
            As[node * LDA + k] =
                f2tf32(nf[(size_t)(nodeBase + node) * 512 + 128 + 3 * k + a]);
        }
    }
    // ---- stage B (128 k x 64 cols) as tf32 ----
#pragma unroll
    for (int i = 0; i < 8; i++) {
        int idx = i * 256 + tid;                   // float4 index
        int k = idx >> 4, c4 = idx & 15;
        float4 val = *reinterpret_cast<const float4*>(B + k * Ncols + ct * 64 + c4 * 4);
        uint4 o = make_uint4(f2tf32(val.x), f2tf32(val.y), f2tf32(val.z), f2tf32(val.w));
        *reinterpret_cast<uint4*>(&Bs[k * LDB + c4 * 4]) = o;
    }
    __syncthreads();

    int warp = tid >> 5, lane = tid & 31;
    int wr = warp & 3, wc = warp >> 2;             // warp tile (wr*32 rows, wc*32 cols)
    int gid = lane >> 2, tig = lane & 3;           // groupID, thread-in-group

    float acc[2][4][4];
#pragma unroll
    for (int mt = 0; mt < 2; mt++)
#pragma unroll
        for (int nt = 0; nt < 4; nt++)
#pragma unroll
            for (int r = 0; r < 4; r++) acc[mt][nt][r] = 0.f;

#pragma unroll
    for (int ks = 0; ks < 16; ks++) {
        int k0 = ks * 8;
        uint32_t afr[2][4];
#pragma unroll
        for (int mt = 0; mt < 2; mt++) {
            int rb = wr * 32 + mt * 16;
            afr[mt][0] = As[(rb + gid) * LDA + k0 + tig];
            afr[mt][1] = As[(rb + gid + 8) * LDA + k0 + tig];
            afr[mt][2] = As[(rb + gid) * LDA + k0 + tig + 4];
            afr[mt][3] = As[(rb + gid + 8) * LDA + k0 + tig + 4];
        }
        uint32_t bfr[4][2];
#pragma unroll
        for (int nt = 0; nt < 4; nt++) {
            int cb = wc * 32 + nt * 8;
            bfr[nt][0] = Bs[(k0 + tig) * LDB + cb + gid];
            bfr[nt][1] = Bs[(k0 + tig + 4) * LDB + cb + gid];
        }
#pragma unroll
        for (int mt = 0; mt < 2; mt++)
#pragma unroll
            for (int nt = 0; nt < 4; nt++)
                mma_tf32(acc[mt][nt], afr[mt], bfr[nt]);
    }

    // ---- epilogue ----
    float* C; size_t ldc;
    if (z == 0) { C = g_Y; ldc = 384; }
    else        { C = g_Z + (size_t)(z - 1) * 512; ldc = 1536; }
#pragma unroll
    for (int mt = 0; mt < 2; mt++) {
#pragma unroll
        for (int nt = 0; nt < 4; nt++) {
            size_t row0 = nodeBase + wr * 32 + mt * 16 + gid;
            size_t col  = ct * 64 + wc * 32 + nt * 8 + tig * 2;
            *reinterpret_cast<float2*>(C + row0 * ldc + col) =
                make_float2(acc[mt][nt][0], acc[mt][nt][1]);
            *reinterpret_cast<float2*>(C + (row0 + 8) * ldc + col) =
                make_float2(acc[mt][nt][2], acc[mt][nt][3]);
        }
    }
}

// ---------------- combine: mix GEMM outputs with multipole scalars ----------------
__global__ void combine_kernel(const float* __restrict__ mf, float* __restrict__ out) {
    int n = blockIdx.x;
    int v = threadIdx.x;
    __shared__ __align__(16) float so[1152];

    const float* f = mf + (size_t)n * 9;
    float f0  = f[0];
    float f1a = f[1], f1b = f[2], f1c = f[3];
    float f2a = f[4], f2b = f[5], f2c = f[6], f2d = f[7], f2e = f[8];

    const float* Y = g_Y + (size_t)n * 384 + v;
    float y0 = Y[0], y1 = Y[128], y2 = Y[256];
    const float* Z = g_Z + (size_t)n * 1536 + v;
    float z00 = Z[0],   z10 = Z[512],  z20 = Z[1024];   // j=0: o0 vector path
    float z01 = Z[128], z11 = Z[640],  z21 = Z[1152];   // j=1: o1 f0 path
    float z02 = Z[256], z12 = Z[768],  z22 = Z[1280];   // j=2: o1 C121 path
    float z03 = Z[384], z13 = Z[896],  z23 = Z[1408];   // j=3: o2 C112 path

    const float r2 = 0.7071067811865476f;   // 1/sqrt(2)
    const float r6 = 0.4082482904638631f;   // 1/sqrt(6)
    const float i5 = 0.4472135954999579f;   // 1/sqrt(5)

    float A00 = -f2c * r6 - f2e * r2;
    float A11 = 2.f * f2c * r6;
    float A22 = -f2c * r6 + f2e * r2;
    float A01 = f2b * r2, A02 = f2a * r2, A12 = f2d * r2;

    float o0 = f0 * y0 + f1a * z00 + f1b * z10 + f1c * z20;

    float o1_0 = f1a * y1 + f0 * z01 + i5 * (A00 * z02 + A01 * z12 + A02 * z22);
    float o1_1 = f1b * y1 + f0 * z11 + i5 * (A01 * z02 + A11 * z12 + A12 * z22);
    float o1_2 = f1c * y1 + f0 * z21 + i5 * (A02 * z02 + A12 * z12 + A22 * z22);

    float o2_0 = f2a * y2 + i5 * (f1c * r2 * z03 + f1a * r2 * z23);
    float o2_1 = f2b * y2 + i5 * (f1b * r2 * z03 + f1a * r2 * z13);
    float o2_2 = f2c * y2 + i5 * ((-f1a * z03 + 2.f * f1b * z13 - f1c * z23) * r6);
    float o2_3 = f2d * y2 + i5 * (f1c * r2 * z13 + f1b * r2 * z23);
    float o2_4 = f2e * y2 + i5 * ((-f1a * z03 + f1c * z23) * r2);

    float* s = so + v * 9;
    s[0] = o0;
    s[1] = o1_0; s[2] = o1_1; s[3] = o1_2;
    s[4] = o2_0; s[5] = o2_1; s[6] = o2_2; s[7] = o2_3; s[8] = o2_4;
    __syncthreads();

    float4* o4 = reinterpret_cast<float4*>(out + (size_t)n * 1152);
    const float4* s4 = reinterpret_cast<const float4*>(so);
#pragma unroll
    for (int i = v; i < 288; i += 128) o4[i] = s4[i];
}

// ---------------- launch ----------------
extern "C" void kernel_launch(void* const* d_in, const int* in_sizes, int n_in,
                              void* d_out, int out_size) {
    const float* nf   = (const float*)d_in[0];
    const float* mf   = (const float*)d_in[1];
    const float* Wup0 = (const float*)d_in[2];
    const float* Wup1 = (const float*)d_in[3];
    const float* tpw  = (const float*)d_in[4];
    const float* Wl0  = (const float*)d_in[5];
    const float* Wl1  = (const float*)d_in[6];
    const float* Wl2  = (const float*)d_in[7];
    float* out = (float*)d_out;

    const int smemBytes = (128 * LDA + 128 * LDB) * 4;   // 104448
    cudaFuncSetAttribute(gemm_tc, cudaFuncAttributeMaxDynamicSharedMemorySize, smemBytes);

    prep_kernel<<<56, 128>>>(Wup0, Wup1, tpw, Wl0, Wl1, Wl2);
    gemm_tc<<<dim3(NN / 128, 8, 4), 256, smemBytes>>>(nf);
    combine_kernel<<<NN, 128>>>(mf, out);
}

// round 5
// speedup vs baseline: 2.9102x; 2.3162x over previous
#include <cuda_runtime.h>
#include <cstdint>

#define NN 65536

// ---------------- folded weights (prep output, tf32-pre-rounded) ----------------
__device__ float g_U[128 * 384];              // [k][3 sec * 128 v]
__device__ float g_V[128 * 512];              // [k][4 sec * 128 v]

__device__ __forceinline__ uint32_t f2tf32(float f) {
    uint32_t u;
    asm("cvt.rna.tf32.f32 %0, %1;" : "=r"(u) : "f"(f));
    return u;
}

// ---------------- prep: fold W_up, tp_w, CG norms, W_l into U/V ----------------
// grid: 7 sections x 16 u-tiles of 8 = 112 blocks, 128 threads (v)
__global__ void __launch_bounds__(128) prep_kernel(
        const float* __restrict__ Wup0, const float* __restrict__ Wup1,
        const float* __restrict__ tpw,  const float* __restrict__ Wl0,
        const float* __restrict__ Wl1,  const float* __restrict__ Wl2) {
    const float INV_UP = 0.0883883476483184f;   // 1/sqrt(128)
    const float A2 = 0.7071067811865476f;       // 1/sqrt(2)
    const float A3 = 0.5773502691896258f;       // 1/sqrt(3)
    const float N0 = 0.0625f;                   // 1/sqrt(256)
    const float N1 = 0.0510310363079829f;       // 1/sqrt(384)
    const float R3 = 0.5773502691896258f;       // CG 1/sqrt(3)
    const float R5 = 0.4472135954999579f;       // CG 1/sqrt(5)

    int sec = blockIdx.x >> 4;     // 0..6
    int ut  = blockIdx.x & 15;     // u-tile of 8 rows
    int v   = threadIdx.x;         // 0..127

    float coefBase; const float* Wl; int rowOff; int tpwIdx;
    switch (sec) {
        case 0: coefBase = A2 * N0;      Wl = Wl0; rowOff = 0;   tpwIdx = 0; break;
        case 1: coefBase = A3 * N1 * R3; Wl = Wl1; rowOff = 0;   tpwIdx = 1; break;
        case 2: coefBase = A2 * N0 * R5; Wl = Wl2; rowOff = 0;   tpwIdx = 2; break;
        case 3: coefBase = A2 * N0 * R3; Wl = Wl0; rowOff = 128; tpwIdx = 4; break;
        case 4: coefBase = A3 * N1 * R3; Wl = Wl1; rowOff = 128; tpwIdx = 3; break;
        case 5: coefBase = A3 * N1;      Wl = Wl1; rowOff = 256; tpwIdx = 6; break;
        default:coefBase = A2 * N0;      Wl = Wl2; rowOff = 128; tpwIdx = 5; break;
    }
    coefBase *= INV_UP;
    const float* Wup = (sec < 3) ? Wup0 : Wup1;

    __shared__ float sWup[8 * 128];
    __shared__ float scoef[128];
#pragma unroll
    for (int i = 0; i < 8; i++)
        sWup[i * 128 + v] = Wup[(size_t)(ut * 8 + i) * 128 + v];
    scoef[v] = coefBase * tpw[tpwIdx * 128 + v];
    __syncthreads();

    float acc[8];
#pragma unroll
    for (int i = 0; i < 8; i++) acc[i] = 0.f;

#pragma unroll 4
    for (int k = 0; k < 128; k++) {
        float t = scoef[k] * Wl[(size_t)(rowOff + k) * 128 + v];
#pragma unroll
        for (int uu = 0; uu < 8; uu++) acc[uu] += sWup[uu * 128 + k] * t;
    }

#pragma unroll
    for (int uu = 0; uu < 8; uu++) {
        int u = ut * 8 + uu;
        float val = __uint_as_float(f2tf32(acc[uu]));   // pre-round to tf32
        if (sec < 3) g_U[u * 384 + sec * 128 + v] = val;
        else         g_V[u * 512 + (sec - 3) * 128 + v] = val;
    }
}

// ---------------- fused gemm + combine ----------------
// 64 nodes/block, 128 threads (4 warps = 4 m-tiles of 16 nodes).
// Block loops 16 v-tiles of 8 v; each pass computes all 15 output sections
// and writes the final output directly (no Y/Z intermediates).
#define ALD 516                       // A row pitch (floats)
#define BLD 72                        // B row pitch (floats)

// smem float offsets
#define OFF_A   0                     // 64*516       = 33024
#define OFF_B0  33024                 // 128*72       =  9216
#define OFF_B1  42240                 //               9216
#define OFF_OUT 51456                 // 64*72        =  4608
#define OFF_MF  56064                 // 64*9         =   576
#define SMEM_FLOATS 56640             // *4 = 226560 bytes

__device__ __forceinline__ void cp16(uint32_t dst, const void* src) {
    asm volatile("cp.async.cg.shared.global [%0], [%1], 16;" :: "r"(dst), "l"(src));
}
__device__ __forceinline__ void cp_commit() {
    asm volatile("cp.async.commit_group;");
}

__device__ __forceinline__ void mma_tf32(float* d, const uint32_t* a, const uint32_t* b) {
    asm volatile(
        "mma.sync.aligned.m16n8k8.row.col.f32.tf32.tf32.f32 "
        "{%0,%1,%2,%3}, {%4,%5,%6,%7}, {%8,%9}, {%0,%1,%2,%3};"
        : "+f"(d[0]), "+f"(d[1]), "+f"(d[2]), "+f"(d[3])
        : "r"(a[0]), "r"(a[1]), "r"(a[2]), "r"(a[3]), "r"(b[0]), "r"(b[1]));
}

__device__ __forceinline__ void stageB(int vt, uint32_t dstBase, int t) {
#pragma unroll
    for (int i = 0; i < 14; i++) {
        int sec = i >> 1, half = i & 1;
        const float* src = (sec < 3)
            ? (g_U + t * 384 + sec * 128 + vt * 8 + half * 4)
            : (g_V + t * 512 + (sec - 3) * 128 + vt * 8 + half * 4);
        cp16(dstBase + (t * BLD + sec * 8 + half * 4) * 4, src);
    }
}

__global__ void __launch_bounds__(128, 1) fused_kernel(
        const float* __restrict__ nf, const float* __restrict__ mf,
        float* __restrict__ out) {
    extern __shared__ float sm[];
    uint32_t sbase = (uint32_t)__cvta_generic_to_shared(sm);

    int t = threadIdx.x;
    int wid = t >> 5, lane = t & 31;
    int gid = lane >> 2, tig = lane & 3;
    size_t nodeBase = (size_t)blockIdx.x * 64;

    // ---- group 0: A (64 x 512 raw nf rows) + mf + B(vt=0) ----
    {
        const float* srcA = nf + nodeBase * 512;
#pragma unroll
        for (int i = 0; i < 64; i++) {
            int idx = i * 128 + t;
            int node = idx >> 7, f4 = idx & 127;
            cp16(sbase + (OFF_A + node * ALD + f4 * 4) * 4, srcA + (size_t)node * 512 + f4 * 4);
        }
        const float* srcM = mf + nodeBase * 9;
#pragma unroll
        for (int i = 0; i < 2; i++) {
            int idx = i * 128 + t;
            if (idx < 144) cp16(sbase + (OFF_MF + idx * 4) * 4, srcM + idx * 4);
        }
        stageB(0, sbase + OFF_B0 * 4, t);
        cp_commit();
    }

    const float r2 = 0.7071067811865476f;
    const float r6 = 0.4082482904638631f;
    const float i5 = 0.4472135954999579f;

    int rb = wid * 16;
    int r0row = (rb + gid) * ALD;
    int r1row = (rb + gid + 8) * ALD;

    for (int p = 0; p < 16; p++) {
        uint32_t bufCur = sbase + ((p & 1) ? OFF_B1 : OFF_B0) * 4;
        if (p + 1 < 16) {
            stageB(p + 1, sbase + (((p + 1) & 1) ? OFF_B1 : OFF_B0) * 4, t);
            cp_commit();
            asm volatile("cp.async.wait_group 1;");
        } else {
            asm volatile("cp.async.wait_group 0;");
        }
        __syncthreads();

        const float* sB = sm + (((p & 1) ? OFF_B1 : OFF_B0));
        (void)bufCur;

        float acc[15][4];
#pragma unroll
        for (int n = 0; n < 15; n++)
#pragma unroll
            for (int q = 0; q < 4; q++) acc[n][q] = 0.f;

#pragma unroll
        for (int ks = 0; ks < 16; ks++) {
            int kt = ks * 8 + tig;
            uint32_t ar[4][4];
            // s-path A fragments
            ar[0][0] = f2tf32(sm[OFF_A + r0row + kt]);
            ar[0][1] = f2tf32(sm[OFF_A + r1row + kt]);
            ar[0][2] = f2tf32(sm[OFF_A + r0row + kt + 4]);
            ar[0][3] = f2tf32(sm[OFF_A + r1row + kt + 4]);
            // v-path A fragments (interleaved stride-3 layout)
#pragma unroll
            for (int a = 0; a < 3; a++) {
                int c0 = 128 + 3 * kt + a;
                ar[a + 1][0] = f2tf32(sm[OFF_A + r0row + c0]);
                ar[a + 1][1] = f2tf32(sm[OFF_A + r1row + c0]);
                ar[a + 1][2] = f2tf32(sm[OFF_A + r0row + c0 + 12]);
                ar[a + 1][3] = f2tf32(sm[OFF_A + r1row + c0 + 12]);
            }
            uint32_t bf[7][2];
#pragma unroll
            for (int sec = 0; sec < 7; sec++) {
                bf[sec][0] = __float_as_uint(sB[kt * BLD + sec * 8 + gid]);
                bf[sec][1] = __float_as_uint(sB[(kt + 4) * BLD + sec * 8 + gid]);
            }
#pragma unroll
            for (int j = 0; j < 3; j++) mma_tf32(acc[j], ar[0], bf[j]);
#pragma unroll
            for (int a = 0; a < 3; a++)
#pragma unroll
                for (int j = 0; j < 4; j++) mma_tf32(acc[3 + a * 4 + j], ar[a + 1], bf[3 + j]);
        }

        // ---- combine (register-local) ----
#pragma unroll
        for (int r = 0; r < 2; r++) {
            int nl = rb + gid + r * 8;
            const float* f = sm + OFF_MF + nl * 9;
            float f0 = f[0];
            float f1a = f[1], f1b = f[2], f1c = f[3];
            float f2a = f[4], f2b = f[5], f2c = f[6], f2d = f[7], f2e = f[8];

            float A00 = -f2c * r6 - f2e * r2;
            float A11 = 2.f * f2c * r6;
            float A22 = -f2c * r6 + f2e * r2;
            float A01 = f2b * r2, A02 = f2a * r2, A12 = f2d * r2;

#pragma unroll
            for (int c = 0; c < 2; c++) {
                int ai = r * 2 + c;
                int vl = tig * 2 + c;
                float y0 = acc[0][ai], y1 = acc[1][ai], y2 = acc[2][ai];
                float z00 = acc[3][ai],  z01 = acc[4][ai],  z02 = acc[5][ai],  z03 = acc[6][ai];
                float z10 = acc[7][ai],  z11 = acc[8][ai],  z12 = acc[9][ai],  z13 = acc[10][ai];
                float z20 = acc[11][ai], z21 = acc[12][ai], z22 = acc[13][ai], z23 = acc[14][ai];

                float* o = sm + OFF_OUT + nl * 72 + vl * 9;
                o[0] = f0 * y0 + f1a * z00 + f1b * z10 + f1c * z20;
                o[1] = f1a * y1 + f0 * z01 + i5 * (A00 * z02 + A01 * z12 + A02 * z22);
                o[2] = f1b * y1 + f0 * z11 + i5 * (A01 * z02 + A11 * z12 + A12 * z22);
                o[3] = f1c * y1 + f0 * z21 + i5 * (A02 * z02 + A12 * z12 + A22 * z22);
                o[4] = f2a * y2 + i5 * (f1c * r2 * z03 + f1a * r2 * z23);
                o[5] = f2b * y2 + i5 * (f1b * r2 * z03 + f1a * r2 * z13);
                o[6] = f2c * y2 + i5 * ((-f1a * z03 + 2.f * f1b * z13 - f1c * z23) * r6);
                o[7] = f2d * y2 + i5 * (f1c * r2 * z13 + f1b * r2 * z23);
                o[8] = f2e * y2 + i5 * ((-f1a * z03 + f1c * z23) * r2);
            }
        }
        __syncthreads();

        // coalesced copy: 64 nodes x 72 floats -> out[n*1152 + vt*72 ..)
#pragma unroll
        for (int i = 0; i < 9; i++) {
            int idx = i * 128 + t;             // 1152 float4s
            int node = idx / 18, f4i = idx - node * 18;
            float4 v4 = *reinterpret_cast<const float4*>(sm + OFF_OUT + node * 72 + f4i * 4);
            *reinterpret_cast<float4*>(out + (nodeBase + node) * 1152 + p * 72 + f4i * 4) = v4;
        }
        __syncthreads();   // protect A/B buffers + OUT region before next pass
    }
}

// ---------------- launch ----------------
extern "C" void kernel_launch(void* const* d_in, const int* in_sizes, int n_in,
                              void* d_out, int out_size) {
    const float* nf   = (const float*)d_in[0];
    const float* mf   = (const float*)d_in[1];
    const float* Wup0 = (const float*)d_in[2];
    const float* Wup1 = (const float*)d_in[3];
    const float* tpw  = (const float*)d_in[4];
    const float* Wl0  = (const float*)d_in[5];
    const float* Wl1  = (const float*)d_in[6];
    const float* Wl2  = (const float*)d_in[7];
    float* out = (float*)d_out;

    static bool attrSet = false;
    if (!attrSet) {
        cudaFuncSetAttribute(fused_kernel, cudaFuncAttributeMaxDynamicSharedMemorySize,
                             SMEM_FLOATS * 4);
        attrSet = true;
    }

    prep_kernel<<<112, 128>>>(Wup0, Wup1, tpw, Wl0, Wl1, Wl2);
    fused_kernel<<<NN / 64, 128, SMEM_FLOATS * 4>>>(nf, mf, out);
}

// round 6
// speedup vs baseline: 3.9874x; 1.3701x over previous
#include <cuda_runtime.h>
#include <cstdint>

#define NN 65536

// ---------------- globals ----------------
__device__ float g_U[128 * 384];              // [k][3 sec * 128 v]  (tf32-pre-rounded)
__device__ float g_V[128 * 512];              // [k][4 sec * 128 v]  (tf32-pre-rounded)
__device__ float g_Bf[16 * 7168];             // fragment-major B per v-tile

__device__ __forceinline__ uint32_t f2tf32(float f) {
    uint32_t u;
    asm("cvt.rna.tf32.f32 %0, %1;" : "=r"(u) : "f"(f));
    return u;
}

// ---------------- prep: fold W_up, tp_w, CG norms, W_l into U/V ----------------
__global__ void __launch_bounds__(128) prep_kernel(
        const float* __restrict__ Wup0, const float* __restrict__ Wup1,
        const float* __restrict__ tpw,  const float* __restrict__ Wl0,
        const float* __restrict__ Wl1,  const float* __restrict__ Wl2) {
    const float INV_UP = 0.0883883476483184f;   // 1/sqrt(128)
    const float A2 = 0.7071067811865476f;       // 1/sqrt(2)
    const float A3 = 0.5773502691896258f;       // 1/sqrt(3)
    const float N0 = 0.0625f;                   // 1/sqrt(256)
    const float N1 = 0.0510310363079829f;       // 1/sqrt(384)
    const float R3 = 0.5773502691896258f;       // CG 1/sqrt(3)
    const float R5 = 0.4472135954999579f;       // CG 1/sqrt(5)

    int sec = blockIdx.x >> 4;     // 0..6
    int ut  = blockIdx.x & 15;     // u-tile of 8 rows
    int v   = threadIdx.x;         // 0..127

    float coefBase; const float* Wl; int rowOff; int tpwIdx;
    switch (sec) {
        case 0: coefBase = A2 * N0;      Wl = Wl0; rowOff = 0;   tpwIdx = 0; break;
        case 1: coefBase = A3 * N1 * R3; Wl = Wl1; rowOff = 0;   tpwIdx = 1; break;
        case 2: coefBase = A2 * N0 * R5; Wl = Wl2; rowOff = 0;   tpwIdx = 2; break;
        case 3: coefBase = A2 * N0 * R3; Wl = Wl0; rowOff = 128; tpwIdx = 4; break;
        case 4: coefBase = A3 * N1 * R3; Wl = Wl1; rowOff = 128; tpwIdx = 3; break;
        case 5: coefBase = A3 * N1;      Wl = Wl1; rowOff = 256; tpwIdx = 6; break;
        default:coefBase = A2 * N0;      Wl = Wl2; rowOff = 128; tpwIdx = 5; break;
    }
    coefBase *= INV_UP;
    const float* Wup = (sec < 3) ? Wup0 : Wup1;

    __shared__ float sWup[8 * 128];
    __shared__ float scoef[128];
#pragma unroll
    for (int i = 0; i < 8; i++)
        sWup[i * 128 + v] = Wup[(size_t)(ut * 8 + i) * 128 + v];
    scoef[v] = coefBase * tpw[tpwIdx * 128 + v];
    __syncthreads();

    float acc[8];
#pragma unroll
    for (int i = 0; i < 8; i++) acc[i] = 0.f;

#pragma unroll 4
    for (int k = 0; k < 128; k++) {
        float tv = scoef[k] * Wl[(size_t)(rowOff + k) * 128 + v];
#pragma unroll
        for (int uu = 0; uu < 8; uu++) acc[uu] += sWup[uu * 128 + k] * tv;
    }

#pragma unroll
    for (int uu = 0; uu < 8; uu++) {
        int u = ut * 8 + uu;
        float val = __uint_as_float(f2tf32(acc[uu]));   // pre-round to tf32
        if (sec < 3) g_U[u * 384 + sec * 128 + v] = val;
        else         g_V[u * 512 + (sec - 3) * 128 + v] = val;
    }
}

// ---------------- repack U/V into fragment-major per-v-tile layout ----------------
// Per v-tile vt (0..15), 7168 floats:
//  [0,2048):    [ks][lane][4]  values (sec0 b0,b1, sec1 b0,b1)
//  [2048,4096): [ks][lane][4]  values (sec2 b0,b1, sec3 b0,b1)
//  [4096,6144): [ks][lane][4]  values (sec4 b0,b1, sec5 b0,b1)
//  [6144,7168): [ks][lane][2]  values (sec6 b0,b1)
// where lane=(gid<<2)|tig, b_h = B[k=ks*8+tig+4h][col=sec*128 + vt*8+gid]
__global__ void __launch_bounds__(256) repack_kernel() {
    int vt = blockIdx.x;
    float* dst = g_Bf + vt * 7168;
    for (int s = threadIdx.x; s < 512; s += 256) {
        int ks = s >> 5, lane = s & 31;
        int gid = lane >> 2, tig = lane & 3;
        int col = vt * 8 + gid;
#pragma unroll
        for (int sec = 0; sec < 7; sec++) {
#pragma unroll
            for (int h = 0; h < 2; h++) {
                int k = ks * 8 + tig + 4 * h;
                float val = (sec < 3) ? g_U[k * 384 + sec * 128 + col]
                                      : g_V[k * 512 + (sec - 3) * 128 + col];
                int i2 = 2 * sec + h;
                int off;
                if (i2 < 12) off = (i2 >> 2) * 2048 + (ks * 32 + lane) * 4 + (i2 & 3);
                else         off = 6144 + (ks * 32 + lane) * 2 + (i2 - 12);
                dst[off] = val;
            }
        }
    }
}

// ---------------- fused gemm + combine ----------------
// 64 nodes/block, 256 threads = 8 warps = 2 groups x 4 m-tiles of 16 rows.
// Group g processes v-tile passes p = 2i+g (8 passes each), own B buffer,
// prefetch overlapped with combine/store; groups hide each other's stalls.
#define ALD 516

// smem float offsets
#define OFF_A   0                     // 64*516  = 33024
#define OFF_B   33024                 // 2*7168  = 14336
#define OFF_O   47360                 // 2*4608  =  9216
#define OFF_MF  56576                 //            576
#define SMEM_FLOATS 57152             // *4 = 228608 bytes

__device__ __forceinline__ void cp16(uint32_t dst, const void* src) {
    asm volatile("cp.async.cg.shared.global [%0], [%1], 16;" :: "r"(dst), "l"(src));
}
__device__ __forceinline__ void cp_commit() {
    asm volatile("cp.async.commit_group;");
}
__device__ __forceinline__ void group_bar(int id) {
    asm volatile("bar.sync %0, 128;" :: "r"(id) : "memory");
}

__device__ __forceinline__ void mma_tf32(float* d, const uint32_t* a, const uint32_t* b) {
    asm volatile(
        "mma.sync.aligned.m16n8k8.row.col.f32.tf32.tf32.f32 "
        "{%0,%1,%2,%3}, {%4,%5,%6,%7}, {%8,%9}, {%0,%1,%2,%3};"
        : "+f"(d[0]), "+f"(d[1]), "+f"(d[2]), "+f"(d[3])
        : "r"(a[0]), "r"(a[1]), "r"(a[2]), "r"(a[3]), "r"(b[0]), "r"(b[1]));
}

__global__ void __launch_bounds__(256, 1) fused_kernel(
        const float* __restrict__ nf, const float* __restrict__ mf,
        float* __restrict__ out) {
    extern __shared__ float sm[];
    uint32_t sbase = (uint32_t)__cvta_generic_to_shared(sm);

    int t = threadIdx.x;                 // 0..255
    int wid = t >> 5, lane = t & 31;
    int grp = wid >> 2;                  // 0/1
    int wg  = wid & 3;                   // m-tile within group
    int gt  = t & 127;                   // thread-in-group
    int gid = lane >> 2, tig = lane & 3;
    size_t nodeBase = (size_t)blockIdx.x * 64;

    // ---- initial staging: A raw + mf + group's first B tile ----
    {
        const float* srcA = nf + nodeBase * 512;
#pragma unroll
        for (int i = 0; i < 32; i++) {
            int idx = i * 256 + t;
            int node = idx >> 7, f4 = idx & 127;
            cp16(sbase + (OFF_A + node * ALD + f4 * 4) * 4, srcA + (size_t)node * 512 + f4 * 4);
        }
        if (t < 144) cp16(sbase + (OFF_MF + t * 4) * 4, mf + nodeBase * 9 + t * 4);
        const float* srcB = g_Bf + (size_t)grp * 7168;   // first pass p0 = grp
#pragma unroll
        for (int i = 0; i < 14; i++) {
            int idx = i * 128 + gt;
            cp16(sbase + (OFF_B + grp * 7168 + idx * 4) * 4, srcB + idx * 4);
        }
        cp_commit();
    }
    asm volatile("cp.async.wait_group 0;");
    __syncthreads();

    // ---- in-place tf32 conversion of A (once) ----
#pragma unroll
    for (int i = 0; i < 33; i++) {
        int idx = i * 256 + t;
        if (idx < 8256) {
            float4 v4 = *reinterpret_cast<float4*>(sm + idx * 4);
            uint4 o = make_uint4(f2tf32(v4.x), f2tf32(v4.y), f2tf32(v4.z), f2tf32(v4.w));
            *reinterpret_cast<uint4*>(sm + idx * 4) = o;
        }
    }
    __syncthreads();

    const float r2 = 0.7071067811865476f;
    const float r6 = 0.4082482904638631f;
    const float i5 = 0.4472135954999579f;

    int rb = wg * 16;
    int r0row = (rb + gid) * ALD;
    int r1row = (rb + gid + 8) * ALD;
    const float* sB = sm + OFF_B + grp * 7168;
    float* sO = sm + OFF_O + grp * 4608;
    int barId = grp + 1;

    for (int i = 0; i < 8; i++) {
        int p = 2 * i + grp;

        asm volatile("cp.async.wait_group 0;");
        group_bar(barId);                      // B[p] visible to whole group

        float acc[15][4];
#pragma unroll
        for (int n = 0; n < 15; n++)
#pragma unroll
            for (int q = 0; q < 4; q++) acc[n][q] = 0.f;

#pragma unroll
        for (int ks = 0; ks < 16; ks++) {
            int kt = ks * 8 + tig;
            uint32_t ar[4][4];
            ar[0][0] = __float_as_uint(sm[r0row + kt]);
            ar[0][1] = __float_as_uint(sm[r1row + kt]);
            ar[0][2] = __float_as_uint(sm[r0row + kt + 4]);
            ar[0][3] = __float_as_uint(sm[r1row + kt + 4]);
#pragma unroll
            for (int a = 0; a < 3; a++) {
                int c0 = 128 + 3 * kt + a;
                ar[a + 1][0] = __float_as_uint(sm[r0row + c0]);
                ar[a + 1][1] = __float_as_uint(sm[r1row + c0]);
                ar[a + 1][2] = __float_as_uint(sm[r0row + c0 + 12]);
                ar[a + 1][3] = __float_as_uint(sm[r1row + c0 + 12]);
            }
            int slot = (ks * 32 + lane);
            float4 b01 = *reinterpret_cast<const float4*>(sB + slot * 4);
            float4 b23 = *reinterpret_cast<const float4*>(sB + 2048 + slot * 4);
            float4 b45 = *reinterpret_cast<const float4*>(sB + 4096 + slot * 4);
            float2 b6  = *reinterpret_cast<const float2*>(sB + 6144 + slot * 2);
            uint32_t bf[7][2] = {
                {__float_as_uint(b01.x), __float_as_uint(b01.y)},
                {__float_as_uint(b01.z), __float_as_uint(b01.w)},
                {__float_as_uint(b23.x), __float_as_uint(b23.y)},
                {__float_as_uint(b23.z), __float_as_uint(b23.w)},
                {__float_as_uint(b45.x), __float_as_uint(b45.y)},
                {__float_as_uint(b45.z), __float_as_uint(b45.w)},
                {__float_as_uint(b6.x),  __float_as_uint(b6.y)}};
#pragma unroll
            for (int j = 0; j < 3; j++) mma_tf32(acc[j], ar[0], bf[j]);
#pragma unroll
            for (int a = 0; a < 3; a++)
#pragma unroll
                for (int j = 0; j < 4; j++) mma_tf32(acc[3 + a * 4 + j], ar[a + 1], bf[3 + j]);
        }

        group_bar(barId);                      // group done reading B[p]
        if (i < 7) {                           // prefetch B[p+2] (overlaps combine/store)
            const float* srcB = g_Bf + (size_t)(p + 2) * 7168;
#pragma unroll
            for (int q = 0; q < 14; q++) {
                int idx = q * 128 + gt;
                cp16(sbase + (OFF_B + grp * 7168 + idx * 4) * 4, srcB + idx * 4);
            }
            cp_commit();
        }

        // ---- combine (register-local) ----
#pragma unroll
        for (int r = 0; r < 2; r++) {
            int nl = rb + gid + r * 8;
            const float* f = sm + OFF_MF + nl * 9;
            float f0 = f[0];
            float f1a = f[1], f1b = f[2], f1c = f[3];
            float f2a = f[4], f2b = f[5], f2c = f[6], f2d = f[7], f2e = f[8];

            float A00 = -f2c * r6 - f2e * r2;
            float A11 = 2.f * f2c * r6;
            float A22 = -f2c * r6 + f2e * r2;
            float A01 = f2b * r2, A02 = f2a * r2, A12 = f2d * r2;

#pragma unroll
            for (int c = 0; c < 2; c++) {
                int ai = r * 2 + c;
                int vl = tig * 2 + c;
                float y0 = acc[0][ai], y1 = acc[1][ai], y2 = acc[2][ai];
                float z00 = acc[3][ai],  z01 = acc[4][ai],  z02 = acc[5][ai],  z03 = acc[6][ai];
                float z10 = acc[7][ai],  z11 = acc[8][ai],  z12 = acc[9][ai],  z13 = acc[10][ai];
                float z20 = acc[11][ai], z21 = acc[12][ai], z22 = acc[13][ai], z23 = acc[14][ai];

                float* o = sO + nl * 72 + vl * 9;
                o[0] = f0 * y0 + f1a * z00 + f1b * z10 + f1c * z20;
                o[1] = f1a * y1 + f0 * z01 + i5 * (A00 * z02 + A01 * z12 + A02 * z22);
                o[2] = f1b * y1 + f0 * z11 + i5 * (A01 * z02 + A11 * z12 + A12 * z22);
                o[3] = f1c * y1 + f0 * z21 + i5 * (A02 * z02 + A12 * z12 + A22 * z22);
                o[4] = f2a * y2 + i5 * (f1c * r2 * z03 + f1a * r2 * z23);
                o[5] = f2b * y2 + i5 * (f1b * r2 * z03 + f1a * r2 * z13);
                o[6] = f2c * y2 + i5 * ((-f1a * z03 + 2.f * f1b * z13 - f1c * z23) * r6);
                o[7] = f2d * y2 + i5 * (f1c * r2 * z13 + f1b * r2 * z23);
                o[8] = f2e * y2 + i5 * ((-f1a * z03 + f1c * z23) * r2);
            }
        }
        group_bar(barId);                      // out tile staged

        // coalesced store: 64 nodes x 72 floats -> out[n*1152 + p*72 ..)
#pragma unroll
        for (int q = 0; q < 9; q++) {
            int idx = q * 128 + gt;            // 1152 float4s
            int node = idx / 18, f4i = idx - node * 18;
            float4 v4 = *reinterpret_cast<const float4*>(sO + node * 72 + f4i * 4);
            *reinterpret_cast<float4*>(out + (nodeBase + node) * 1152 + p * 72 + f4i * 4) = v4;
        }
        group_bar(barId);                      // out buffer free for next pass
    }
}

// ---------------- launch ----------------
extern "C" void kernel_launch(void* const* d_in, const int* in_sizes, int n_in,
                              void* d_out, int out_size) {
    const float* nf   = (const float*)d_in[0];
    const float* mf   = (const float*)d_in[1];
    const float* Wup0 = (const float*)d_in[2];
    const float* Wup1 = (const float*)d_in[3];
    const float* tpw  = (const float*)d_in[4];
    const float* Wl0  = (const float*)d_in[5];
    const float* Wl1  = (const float*)d_in[6];
    const float* Wl2  = (const float*)d_in[7];
    float* out = (float*)d_out;

    static bool attrSet = false;
    if (!attrSet) {
        cudaFuncSetAttribute(fused_kernel, cudaFuncAttributeMaxDynamicSharedMemorySize,
                             SMEM_FLOATS * 4);
        attrSet = true;
    }

    prep_kernel<<<112, 128>>>(Wup0, Wup1, tpw, Wl0, Wl1, Wl2);
    repack_kernel<<<16, 256>>>();
    fused_kernel<<<NN / 64, 256, SMEM_FLOATS * 4>>>(nf, mf, out);
}